// round 8
// baseline (speedup 1.0000x reference)
#include <cuda_runtime.h>

#define CC 64
#define TT 256
#define VV 25
#define NN 128
#define TC 16              /* t per block */
#define POS 400            /* TC*VV */
#define NPOS 819200.0f
#define NTHR 416           /* 13 warps */
#define TILE 25600         /* CC*TC*VV floats per (n,tc) tile */
#define XS_FLOATS (CC * POS)           /* 25600 */
#define GSMEM ((XS_FLOATS + 128) * 4)  /* 102912 B */
#define ESTR 401
#define ESMEM ((CC * ESTR + 128) * 4)  /* 103168 B */
#define TOTEL 52428800

typedef unsigned long long ull;

// Device globals (no runtime allocation). g_Wf padded so the one-channel-ahead
// prefetch on c=63 never faults.
__device__ __align__(16) float g_Wf[VV * CC * CC + 64];  // [v][c][o4][og], o=og*16+o4
__device__ __align__(16) float g_B[CC];
__device__ float g_sum[CC];
__device__ float g_sumsq[CC];
__device__ float g_scale[CC];
__device__ float g_shift[CC];
// hidden in BLOCKED layout: [n][tc][v][og][th][tp][o4][j]  (j = t-pair lane)
__device__ float g_hid[TOTEL];

__device__ __forceinline__ void ffma2(ull& d, ull a, ull b) {
    asm("fma.rn.f32x2 %0, %1, %2, %0;" : "+l"(d) : "l"(a), "l"(b));
}
__device__ __forceinline__ ull packrep(float v) {
    ull r; asm("mov.b64 %0, {%1,%1};" : "=l"(r) : "f"(v)); return r;
}
__device__ __forceinline__ void unpack2(ull p, float& a, float& b) {
    asm("mov.b64 {%0,%1}, %2;" : "=f"(a), "=f"(b) : "l"(p));
}

// ---------------------------------------------------------------------------
// k0: softmax rows sum to 1 -> attention collapses to s_i[v] = 1 + sum_w(A+GA).
// g_Wf[((v*64+c)*16+o4)*4+og] = sum_i s_i[v] * gw[i][o][c], o = og*16+o4
// (one lane's 4 o-weights = one 16B float4). B = sum_i gb[i]; zero stats.
// ---------------------------------------------------------------------------
__global__ void k0(const float* __restrict__ A, const float* __restrict__ GA,
                   const float* __restrict__ gw, const float* __restrict__ gb) {
    __shared__ float s_sh[75];
    int tid = threadIdx.x;
    if (tid < 75) {
        const float* a = A + tid * 25;
        const float* g = GA + tid * 25;
        float s = 1.f;
        for (int w = 0; w < 25; w++) s += a[w] + g[w];
        s_sh[tid] = s;
    }
    if (blockIdx.x == 0 && tid < CC) {
        g_sum[tid] = 0.f;
        g_sumsq[tid] = 0.f;
        float b = 0.f;
        for (int i = 0; i < 3; i++) b += gb[i * CC + tid];
        g_B[tid] = b;
    }
    __syncthreads();
    for (int idx = blockIdx.x * blockDim.x + tid; idx < VV * CC * CC;
         idx += gridDim.x * blockDim.x) {
        int og = idx & 3;
        int o4 = (idx >> 2) & 15;
        int c = (idx >> 6) & 63;
        int v = idx >> 12;
        int o = og * 16 + o4;
        float w = 0.f;
        for (int i = 0; i < 3; i++)
            w += s_sh[i * 25 + v] * gw[(i * CC + o) * CC + c];
        g_Wf[idx] = w;
    }
}

// ---------------------------------------------------------------------------
// gemmst: block=(tc of 16 t, n), 13 warps, occupancy 2. Warp = vertex v
// (rounds v, v+13). lane = (o4 0..15, th 0..1). f32x2 packs T-PAIRS:
// acc[og][tp] covers o=og*16+o4, t={th*8+2tp, +1}. x operand = contiguous
// t-pair LDS.64 broadcast from xs[c][tp][v][2]; weight = ONE LDG.128 per
// thread-channel (4 o's, reused over 16 t) + mov-replicated. Hidden leaves
// in registers -> blocked-layout STG.64 (2 wavefronts) -- no smem transpose.
// Stats: in-register -> smem atomics -> per-block global atomics.
// ---------------------------------------------------------------------------
__global__ void __launch_bounds__(NTHR, 2)
gemmst(const float* __restrict__ x) {
    extern __shared__ float smem[];
    float* xs = smem;                 // [c][tp][v][2] = [64][400]
    float* aux = smem + XS_FLOATS;    // stats[128]
    int tid = threadIdx.x;
    int tc = blockIdx.x, n = blockIdx.y;

    if (tid < 128) aux[tid] = 0.f;

    // staging: thread owns fixed r = t*25+v, walks 64 channels.
    // global read coalesced; STS stride-2 (2-way worst case).
    if (tid < POS) {
        int r = tid;
        int t = r / 25, v = r - t * 25;
        int sx = (t >> 1) * 50 + v * 2 + (t & 1);
        const float* src = x + (size_t)n * 409600 + tc * POS + r;
#pragma unroll 4
        for (int c = 0; c < CC; c++)
            xs[c * POS + sx] = src[c * 6400];
    }
    __syncthreads();

    int warp = tid >> 5, lane = tid & 31;
    int o4 = lane & 15, th = lane >> 4;

    for (int v = warp; v < VV; v += 13) {
        ull acc[4][4];                 // [og][tp]
#pragma unroll
        for (int og = 0; og < 4; og++) {
            ull b = packrep(g_B[og * 16 + o4]);
#pragma unroll
            for (int tp = 0; tp < 4; tp++) acc[og][tp] = b;
        }

        const float4* wp = (const float4*)(g_Wf + v * 4096) + o4;  // + c*16
        const ull* xb = (const ull*)xs + th * 100 + v;             // + c*200 + tp*25

        float4 w = wp[0];
#pragma unroll 2
        for (int c = 0; c < CC; c++) {
            float4 nw = wp[(c + 1) * 16];          // prefetch (padded)
            ull w0 = packrep(w.x), w1 = packrep(w.y);
            ull w2 = packrep(w.z), w3 = packrep(w.w);
#pragma unroll
            for (int tp = 0; tp < 4; tp++) {
                ull xv = xb[c * 200 + tp * 25];
                ffma2(acc[0][tp], w0, xv);
                ffma2(acc[1][tp], w1, xv);
                ffma2(acc[2][tp], w2, xv);
                ffma2(acc[3][tp], w3, xv);
            }
            w = nw;
        }

        // stats (every (o,t,v) counted exactly once grid-wide)
#pragma unroll
        for (int og = 0; og < 4; og++) {
            int o = og * 16 + o4;
            float s = 0.f, q = 0.f;
#pragma unroll
            for (int tp = 0; tp < 4; tp++) {
                float h0, h1;
                unpack2(acc[og][tp], h0, h1);
                s += h0 + h1;
                q += h0 * h0 + h1 * h1;
            }
            atomicAdd(&aux[o], s);
            atomicAdd(&aux[64 + o], q);
        }

        // blocked store: ull idx within tile = v*512 + og*128 + th*64 + tp*16 + o4
        ull* dst = (ull*)g_hid + ((size_t)n * 16 + tc) * 12800 + v * 512 + th * 64 + o4;
#pragma unroll
        for (int og = 0; og < 4; og++)
#pragma unroll
            for (int tp = 0; tp < 4; tp++)
                dst[og * 128 + tp * 16] = acc[og][tp];
    }
    __syncthreads();

    if (tid < 64) atomicAdd(&g_sum[tid], aux[tid]);
    else if (tid < 128) atomicAdd(&g_sumsq[tid - 64], aux[tid]);
}

// ---------------------------------------------------------------------------
// kbn: training-mode biased-var BN folded to per-channel scale/shift.
// ---------------------------------------------------------------------------
__global__ void kbn(const float* __restrict__ gamma, const float* __restrict__ beta) {
    int o = threadIdx.x;
    if (o < CC) {
        float m = g_sum[o] * (1.0f / NPOS);
        float var = g_sumsq[o] * (1.0f / NPOS) - m * m;
        float r = rsqrtf(var + 1e-5f);
        float sc = gamma[o] * r;
        g_scale[o] = sc;
        g_shift[o] = beta[o] - m * sc;
    }
}

// ---------------------------------------------------------------------------
// epi: per-(n,tc) tile. Phase 1: read blocked hid tile coalesced (float4),
// scatter-decode into hsm[o][t*25+v] (stride 401 -> conflict-light).
// Phase 2: out = relu(hid*scale+shift + x), fully coalesced per channel row.
// ---------------------------------------------------------------------------
__global__ void __launch_bounds__(512, 2) epi(const float* __restrict__ x,
                                              float* __restrict__ out) {
    extern __shared__ float hsm[];            // [64][401]
    float* sc_sh = hsm + CC * ESTR;
    float* sf_sh = sc_sh + 64;
    int tid = threadIdx.x;
    int tc = blockIdx.x, n = blockIdx.y;

    if (tid < 64) { sc_sh[tid] = g_scale[tid]; sf_sh[tid] = g_shift[tid]; }

    const float4* hb = (const float4*)(g_hid + ((size_t)n * 16 + tc) * TILE);
#pragma unroll 1
    for (int i4 = tid; i4 < TILE / 4; i4 += 512) {
        float4 h = hb[i4];
        int base = i4 * 4;
        int v = base >> 10;
        int og = (base >> 8) & 3;
        int th = (base >> 7) & 1;
        int tp = (base >> 5) & 3;
        int o4 = (base >> 1) & 15;
        int o = og * 16 + o4;
        int t = th * 8 + tp * 2;
        float* p0 = hsm + o * ESTR + t * 25 + v;
        p0[0] = h.x;
        p0[25] = h.y;                 // j=1 -> t+1
        p0[ESTR] = h.z;               // o4+1
        p0[ESTR + 25] = h.w;
    }
    __syncthreads();

    if (tid < POS) {
        size_t xoff = (size_t)n * 409600 + tc * POS + tid;
        const float* xp = x + xoff;
        float* op = out + xoff;
#pragma unroll 4
        for (int c = 0; c < CC; c++) {
            float val = fmaf(hsm[c * ESTR + tid], sc_sh[c], sf_sh[c]) + xp[c * 6400];
            op[c * 6400] = fmaxf(val, 0.f);
        }
    }
}

extern "C" void kernel_launch(void* const* d_in, const int* in_sizes, int n_in,
                              void* d_out, int out_size) {
    const float* x     = (const float*)d_in[0];
    const float* A     = (const float*)d_in[1];
    const float* GA    = (const float*)d_in[2];
    const float* gw    = (const float*)d_in[7];
    const float* gb    = (const float*)d_in[8];
    const float* gamma = (const float*)d_in[9];
    const float* beta  = (const float*)d_in[10];
    float* out = (float*)d_out;
    (void)in_sizes; (void)n_in; (void)out_size;

    cudaFuncSetAttribute(gemmst, cudaFuncAttributeMaxDynamicSharedMemorySize, GSMEM);
    cudaFuncSetAttribute(epi, cudaFuncAttributeMaxDynamicSharedMemorySize, ESMEM);

    k0<<<52, 256>>>(A, GA, gw, gb);
    gemmst<<<dim3(TT / TC, NN), NTHR, GSMEM>>>(x);
    kbn<<<1, 64>>>(gamma, beta);
    epi<<<dim3(TT / TC, NN), 512, ESMEM>>>(x, out);
}

// round 9
// speedup vs baseline: 1.3732x; 1.3732x over previous
#include <cuda_runtime.h>

#define CC 64
#define TT 256
#define VV 25
#define NN 128
#define TC 16              /* t per block */
#define POS 400            /* TC*VV */
#define NPOS 819200.0f
#define NTHR 416           /* 13 warps */
#define TILE 25600         /* CC*TC*VV floats per (n,tc) tile */
#define XS_FLOATS (CC * POS)           /* 25600 */
#define GSMEM ((XS_FLOATS + 128) * 4)  /* 102912 B */
#define HSTR2 33
#define ESMEM ((POS * HSTR2 + 128) * 4)  /* 53312 B -> 4 blocks/SM */
#define TOTEL 52428800

typedef unsigned long long ull;

// Device globals (no runtime allocation). g_Wf padded +256 so the TWO-channel
// -ahead prefetch (c+2 <= 65) never faults.
__device__ __align__(16) float g_Wf[VV * CC * CC + 256];  // [v][c][o4][og], o=og*16+o4
__device__ __align__(16) float g_B[CC];
__device__ float g_s[75];
__device__ float g_sum[CC];
__device__ float g_sumsq[CC];
__device__ float g_scale[CC];
__device__ float g_shift[CC];
// hidden in BLOCKED layout: [n][tc][v][og][th][tp][o4][j]  (j = t-pair lane)
__device__ float g_hid[TOTEL];

__device__ __forceinline__ void ffma2(ull& d, ull a, ull b) {
    asm("fma.rn.f32x2 %0, %1, %2, %0;" : "+l"(d) : "l"(a), "l"(b));
}
__device__ __forceinline__ ull packrep(float v) {
    ull r; asm("mov.b64 %0, {%1,%1};" : "=l"(r) : "f"(v)); return r;
}
__device__ __forceinline__ void unpack2(ull p, float& a, float& b) {
    asm("mov.b64 {%0,%1}, %2;" : "=f"(a), "=f"(b) : "l"(p));
}

// ---------------------------------------------------------------------------
// k0a: softmax rows sum to 1 -> attention collapses to s_i[v] = 1+sum_w(A+GA).
// Compute g_s, B = sum_i gb[i], zero stat accumulators. One tiny block.
// ---------------------------------------------------------------------------
__global__ void k0a(const float* __restrict__ A, const float* __restrict__ GA,
                    const float* __restrict__ gb) {
    int tid = threadIdx.x;
    if (tid < 75) {
        const float* a = A + tid * 25;
        const float* g = GA + tid * 25;
        float s = 1.f;
        for (int w = 0; w < 25; w++) s += a[w] + g[w];
        g_s[tid] = s;
    }
    if (tid < CC) {
        g_sum[tid] = 0.f;
        g_sumsq[tid] = 0.f;
        float b = 0.f;
        for (int i = 0; i < 3; i++) b += gb[i * CC + tid];
        g_B[tid] = b;
    }
}

// ---------------------------------------------------------------------------
// k0b: build folded weights for v in [vbase, vbase+13): 
//   g_Wf[((v*64+c)*16+o4)*4+og] = sum_i s_i[v]*gw[i][o][c], o = og*16+o4.
// Two instances (vbase 0, 13) so gemmst sits at captured launch index 3.
// ---------------------------------------------------------------------------
__global__ void k0b(const float* __restrict__ gw, int vbase) {
    __shared__ float s_sh[75];
    int tid = threadIdx.x;
    if (tid < 75) s_sh[tid] = g_s[tid];
    __syncthreads();
    int nv = (vbase + 13 <= VV) ? 13 : (VV - vbase);
    for (int li = blockIdx.x * blockDim.x + tid; li < nv * CC * CC;
         li += gridDim.x * blockDim.x) {
        int og = li & 3;
        int o4 = (li >> 2) & 15;
        int c = (li >> 6) & 63;
        int v = vbase + (li >> 12);
        int o = og * 16 + o4;
        float w = 0.f;
        for (int i = 0; i < 3; i++)
            w += s_sh[i * 25 + v] * gw[(i * CC + o) * CC + c];
        g_Wf[(size_t)v * 4096 + (li & 4095)] = w;
    }
}

// ---------------------------------------------------------------------------
// gemmst: block=(tc of 16 t, n), 13 warps, occupancy 2. Warp = vertex v
// (rounds v, v+13). lane = (o4, th). f32x2 packs T-PAIRS: acc[og][tp] covers
// o=og*16+o4, t={th*8+2tp,+1}. x = t-pair LDS.64 broadcast; weight = one
// LDG.128/thread-channel, prefetched TWO channels ahead (per-warp wall
// coverage ~416 cyc > 262-cyc L2 hit latency). Hidden leaves in registers
// as blocked-layout STG.64. Stats via smem atomics -> global atomics.
// ---------------------------------------------------------------------------
__global__ void __launch_bounds__(NTHR, 2)
gemmst(const float* __restrict__ x) {
    extern __shared__ float smem[];
    float* xs = smem;                 // [c][tp][v][2] = [64][400]
    float* aux = smem + XS_FLOATS;    // stats[128]
    int tid = threadIdx.x;
    int tc = blockIdx.x, n = blockIdx.y;

    if (tid < 128) aux[tid] = 0.f;

    // float4 staging: 6400 float4 loads, scattered 4x STS.32 each
    {
        const float4* src4 = (const float4*)(x + (size_t)n * 409600 + tc * POS);
        for (int f = tid; f < 6400; f += NTHR) {
            int c = f / 100, q = f - c * 100;
            float4 val = src4[c * 1600 + q];
            int r = q * 4;
            int t = r / 25, v = r - t * 25;
            float* xc = xs + c * POS;
            float e[4] = {val.x, val.y, val.z, val.w};
#pragma unroll
            for (int j = 0; j < 4; j++) {
                int vv = v + j, tt = t;
                if (vv >= 25) { vv -= 25; tt++; }
                xc[(tt >> 1) * 50 + vv * 2 + (tt & 1)] = e[j];
            }
        }
    }
    __syncthreads();

    int warp = tid >> 5, lane = tid & 31;
    int o4 = lane & 15, th = lane >> 4;

    for (int v = warp; v < VV; v += 13) {
        ull acc[4][4];                 // [og][tp]
#pragma unroll
        for (int og = 0; og < 4; og++) {
            ull b = packrep(g_B[og * 16 + o4]);
#pragma unroll
            for (int tp = 0; tp < 4; tp++) acc[og][tp] = b;
        }

        const float4* wp = (const float4*)(g_Wf + (size_t)v * 4096) + o4;  // + c*16
        const ull* xb = (const ull*)xs + th * 100 + v;                     // + c*200 + tp*25

        float4 w = wp[0];
        float4 wn = wp[16];
#pragma unroll 2
        for (int c = 0; c < CC; c++) {
            float4 wn2 = wp[(c + 2) * 16];         // depth-2 prefetch (padded)
            ull w0 = packrep(w.x), w1 = packrep(w.y);
            ull w2 = packrep(w.z), w3 = packrep(w.w);
#pragma unroll
            for (int tp = 0; tp < 4; tp++) {
                ull xv = xb[c * 200 + tp * 25];
                ffma2(acc[0][tp], w0, xv);
                ffma2(acc[1][tp], w1, xv);
                ffma2(acc[2][tp], w2, xv);
                ffma2(acc[3][tp], w3, xv);
            }
            w = wn; wn = wn2;
        }

        // stats (every (o,t,v) counted exactly once grid-wide)
#pragma unroll
        for (int og = 0; og < 4; og++) {
            int o = og * 16 + o4;
            float s = 0.f, q = 0.f;
#pragma unroll
            for (int tp = 0; tp < 4; tp++) {
                float h0, h1;
                unpack2(acc[og][tp], h0, h1);
                s += h0 + h1;
                q += h0 * h0 + h1 * h1;
            }
            atomicAdd(&aux[o], s);
            atomicAdd(&aux[64 + o], q);
        }

        // blocked store: ull idx in tile = v*512 + og*128 + th*64 + tp*16 + o4
        ull* dst = (ull*)g_hid + ((size_t)n * 16 + tc) * 12800 + v * 512 + th * 64 + o4;
#pragma unroll
        for (int og = 0; og < 4; og++)
#pragma unroll
            for (int tp = 0; tp < 4; tp++)
                dst[og * 128 + tp * 16] = acc[og][tp];
    }
    __syncthreads();

    if (tid < 64) atomicAdd(&g_sum[tid], aux[tid]);
    else if (tid < 128) atomicAdd(&g_sumsq[tid - 64], aux[tid]);
}

// ---------------------------------------------------------------------------
// kbn: training-mode biased-var BN folded to per-channel scale/shift.
// ---------------------------------------------------------------------------
__global__ void kbn(const float* __restrict__ gamma, const float* __restrict__ beta) {
    int o = threadIdx.x;
    if (o < CC) {
        float m = g_sum[o] * (1.0f / NPOS);
        float var = g_sumsq[o] * (1.0f / NPOS) - m * m;
        float r = rsqrtf(var + 1e-5f);
        float sc = gamma[o] * r;
        g_scale[o] = sc;
        g_shift[o] = beta[o] - m * sc;
    }
}

// ---------------------------------------------------------------------------
// epi: HALF-tile (32 channels) per block -> smem 52.8KB -> 4 blocks/SM,
// occ 100%, grid 4096. Phase 1: read the half's blocked floats (per v one
// contiguous 2KB run), decode into hsm[pos][33] (odd stride: phase-2
// conflict-free). Phase 2: out = relu(hid*scale+shift + x), coalesced.
// ---------------------------------------------------------------------------
__global__ void __launch_bounds__(512, 4) epi(const float* __restrict__ x,
                                              float* __restrict__ out) {
    extern __shared__ float hsm[];            // [400][33]
    float* sc_sh = hsm + POS * HSTR2;
    float* sf_sh = sc_sh + 64;
    int tid = threadIdx.x;
    int bx = blockIdx.x;
    int tc = bx >> 1, h = bx & 1;
    int n = blockIdx.y;

    if (tid < 64) { sc_sh[tid] = g_scale[tid]; sf_sh[tid] = g_shift[tid]; }

    const float4* hb = (const float4*)(g_hid + ((size_t)n * 16 + tc) * TILE);
#pragma unroll 2
    for (int i4 = tid; i4 < 3200; i4 += 512) {
        int v = i4 >> 7, r4 = i4 & 127;
        float4 hv = hb[v * 256 + h * 128 + r4];
        int bf = r4 * 4;
        int og_l = bf >> 8;                   // 0..1
        int th = (bf >> 7) & 1;
        int tp = (bf >> 5) & 3;
        int o4 = (bf >> 1) & 15;              // even
        int ol = og_l * 16 + o4;
        int t = th * 8 + tp * 2;
        float* p = hsm + (t * 25 + v) * HSTR2 + ol;
        p[0] = hv.x;                          // (ol,   t)
        p[25 * HSTR2] = hv.y;                 // (ol,   t+1)
        p[1] = hv.z;                          // (ol+1, t)
        p[25 * HSTR2 + 1] = hv.w;             // (ol+1, t+1)
    }
    __syncthreads();

    if (tid < POS) {
        size_t base = (size_t)n * 409600 + (size_t)h * 32 * 6400 + tc * POS + tid;
        const float* xp = x + base;
        float* op = out + base;
        const float* hrow = hsm + tid * HSTR2;
#pragma unroll 8
        for (int cl = 0; cl < 32; cl++) {
            int c = h * 32 + cl;
            float val = fmaf(hrow[cl], sc_sh[c], sf_sh[c]) + xp[cl * 6400];
            op[cl * 6400] = fmaxf(val, 0.f);
        }
    }
}

extern "C" void kernel_launch(void* const* d_in, const int* in_sizes, int n_in,
                              void* d_out, int out_size) {
    const float* x     = (const float*)d_in[0];
    const float* A     = (const float*)d_in[1];
    const float* GA    = (const float*)d_in[2];
    const float* gw    = (const float*)d_in[7];
    const float* gb    = (const float*)d_in[8];
    const float* gamma = (const float*)d_in[9];
    const float* beta  = (const float*)d_in[10];
    float* out = (float*)d_out;
    (void)in_sizes; (void)n_in; (void)out_size;

    cudaFuncSetAttribute(gemmst, cudaFuncAttributeMaxDynamicSharedMemorySize, GSMEM);
    cudaFuncSetAttribute(epi, cudaFuncAttributeMaxDynamicSharedMemorySize, ESMEM);

    k0a<<<1, 128>>>(A, GA, gb);               // idx 0
    k0b<<<52, 256>>>(gw, 0);                  // idx 1
    k0b<<<52, 256>>>(gw, 13);                 // idx 2
    gemmst<<<dim3(TT / TC, NN), NTHR, GSMEM>>>(x);   // idx 3 -> ncu capture
    kbn<<<1, 64>>>(gamma, beta);
    epi<<<dim3(32, NN), 512, ESMEM>>>(x, out);
}

// round 10
// speedup vs baseline: 1.4495x; 1.0556x over previous
#include <cuda_runtime.h>

#define CC 64
#define TT 256
#define VV 25
#define NN 128
#define TC 16              /* t per block */
#define POS 400            /* TC*VV */
#define NPOS 819200.0f
#define NTHR 416           /* 13 warps */
#define TILE 25600         /* CC*TC*VV floats per (n,tc) tile */
#define XS_FLOATS (CC * POS)           /* 25600 */
#define GSMEM ((XS_FLOATS + 128) * 4)  /* 102912 B */
#define HSTR2 33
#define ESMEM ((POS * HSTR2 + 128) * 4)  /* 53312 B -> 4 blocks/SM */
#define TOTEL 52428800

typedef unsigned long long ull;

// Device globals (no runtime allocation). g_Wf padded +256 so the ping-pong
// prefetch (reads up to c=65) never faults.
__device__ __align__(16) float g_Wf[VV * CC * CC + 256];  // [v][c][o4][og], o=og*16+o4
__device__ __align__(16) float g_B[CC];
__device__ float g_s[75];
__device__ float g_sum[CC];
__device__ float g_sumsq[CC];
__device__ float g_scale[CC];
__device__ float g_shift[CC];
// hidden in BLOCKED layout: [n][tc][v][og][th][tp][o4][j]  (t = th*8+tp*2+j)
__device__ float g_hid[TOTEL];

__device__ __forceinline__ void ffma2(ull& d, ull a, ull b) {
    asm("fma.rn.f32x2 %0, %1, %2, %0;" : "+l"(d) : "l"(a), "l"(b));
}
__device__ __forceinline__ ull packrep(float v) {
    ull r; asm("mov.b64 %0, {%1,%1};" : "=l"(r) : "f"(v)); return r;
}
__device__ __forceinline__ void unpack2(ull p, float& a, float& b) {
    asm("mov.b64 {%0,%1}, %2;" : "=f"(a), "=f"(b) : "l"(p));
}

// ---------------------------------------------------------------------------
// k0a: softmax rows sum to 1 -> attention collapses to s_i[v] = 1+sum_w(A+GA).
// Compute g_s, B = sum_i gb[i], zero stat accumulators. One tiny block.
// ---------------------------------------------------------------------------
__global__ void k0a(const float* __restrict__ A, const float* __restrict__ GA,
                    const float* __restrict__ gb) {
    int tid = threadIdx.x;
    if (tid < 75) {
        const float* a = A + tid * 25;
        const float* g = GA + tid * 25;
        float s = 1.f;
        for (int w = 0; w < 25; w++) s += a[w] + g[w];
        g_s[tid] = s;
    }
    if (tid < CC) {
        g_sum[tid] = 0.f;
        g_sumsq[tid] = 0.f;
        float b = 0.f;
        for (int i = 0; i < 3; i++) b += gb[i * CC + tid];
        g_B[tid] = b;
    }
}

// ---------------------------------------------------------------------------
// k0b: build folded weights for v in [vbase, vbase+13):
//   g_Wf[((v*64+c)*16+o4)*4+og] = sum_i s_i[v]*gw[i][o][c], o = og*16+o4.
// Two instances (vbase 0, 13) so gemmst sits at captured launch index 3.
// ---------------------------------------------------------------------------
__global__ void k0b(const float* __restrict__ gw, int vbase) {
    __shared__ float s_sh[75];
    int tid = threadIdx.x;
    if (tid < 75) s_sh[tid] = g_s[tid];
    __syncthreads();
    int nv = (vbase + 13 <= VV) ? 13 : (VV - vbase);
    for (int li = blockIdx.x * blockDim.x + tid; li < nv * CC * CC;
         li += gridDim.x * blockDim.x) {
        int og = li & 3;
        int o4 = (li >> 2) & 15;
        int c = (li >> 6) & 63;
        int v = vbase + (li >> 12);
        int o = og * 16 + o4;
        float w = 0.f;
        for (int i = 0; i < 3; i++)
            w += s_sh[i * 25 + v] * gw[(i * CC + o) * CC + c];
        g_Wf[(size_t)v * 4096 + (li & 4095)] = w;
    }
}

// ---------------------------------------------------------------------------
// gemmst: block=(tc of 16 t, n), 13 warps, occupancy 2. Warp = vertex v
// (rounds v, v+13). lane = (o4, th). f32x2 packs T-PAIRS j=t&1:
// acc[og][tp] covers o=og*16+o4, t=th*8+tp*2+{0,1}.
// xs laid [c][tp][v][4] with both th-halves ADJACENT (8B apart) -> every
// x LDS.64 is ONE wavefront. Weight = one LDG.128/thread-channel in a
// copy-free ping-pong (wA/wB reloaded in place, distance 2 channels
// ~290 cyc > 262 L2 hit). Hidden leaves in registers as blocked STG.64.
// Stats via smem atomics -> global atomics.
// ---------------------------------------------------------------------------
__global__ void __launch_bounds__(NTHR, 2)
gemmst(const float* __restrict__ x) {
    extern __shared__ float smem[];
    float* xs = smem;                 // [c][tp][v][4]
    float* aux = smem + XS_FLOATS;    // stats[128]
    int tid = threadIdx.x;
    int tc = blockIdx.x, n = blockIdx.y;

    if (tid < 128) aux[tid] = 0.f;

    // float4 staging with interleaved-th scatter:
    // sx(t,v) = ((t&7)>>1)*100 + v*4 + (t>>3)*2 + (t&1)
    {
        const float4* src4 = (const float4*)(x + (size_t)n * 409600 + tc * POS);
        for (int f = tid; f < 6400; f += NTHR) {
            int c = f / 100, q = f - c * 100;
            float4 val = src4[c * 1600 + q];
            int r = q * 4;
            int t = r / 25, v = r - t * 25;
            float* xc = xs + c * POS;
            float e[4] = {val.x, val.y, val.z, val.w};
#pragma unroll
            for (int j = 0; j < 4; j++) {
                int vv = v + j, tt = t;
                if (vv >= 25) { vv -= 25; tt++; }
                xc[((tt & 7) >> 1) * 100 + vv * 4 + ((tt >> 3) << 1) + (tt & 1)] = e[j];
            }
        }
    }
    __syncthreads();

    int warp = tid >> 5, lane = tid & 31;
    int o4 = lane & 15, th = lane >> 4;

    for (int v = warp; v < VV; v += 13) {
        ull acc[4][4];                 // [og][tp]
#pragma unroll
        for (int og = 0; og < 4; og++) {
            ull b = packrep(g_B[og * 16 + o4]);
#pragma unroll
            for (int tp = 0; tp < 4; tp++) acc[og][tp] = b;
        }

        const float4* wp = (const float4*)(g_Wf + (size_t)v * 4096) + o4;  // + c*16
        const ull* xb = (const ull*)xs + v * 2 + th;                       // + c*200 + tp*50

        auto dochan = [&](int c, float4 w) {
            ull w0 = packrep(w.x), w1 = packrep(w.y);
            ull w2 = packrep(w.z), w3 = packrep(w.w);
#pragma unroll
            for (int tp = 0; tp < 4; tp++) {
                ull xv = xb[c * 200 + tp * 50];
                ffma2(acc[0][tp], w0, xv);
                ffma2(acc[1][tp], w1, xv);
                ffma2(acc[2][tp], w2, xv);
                ffma2(acc[3][tp], w3, xv);
            }
        };

        float4 wA = wp[0];
        float4 wB = wp[16];
#pragma unroll 2
        for (int cc = 0; cc < 32; cc++) {
            int c0 = 2 * cc;
            dochan(c0, wA);
            wA = wp[(c0 + 2) * 16];        // reload in place: no copy movs
            dochan(c0 + 1, wB);
            wB = wp[(c0 + 3) * 16];        // (padded: c<=65 never faults)
        }

        // stats (every (o,t,v) counted exactly once grid-wide)
#pragma unroll
        for (int og = 0; og < 4; og++) {
            int o = og * 16 + o4;
            float s = 0.f, q = 0.f;
#pragma unroll
            for (int tp = 0; tp < 4; tp++) {
                float h0, h1;
                unpack2(acc[og][tp], h0, h1);
                s += h0 + h1;
                q += h0 * h0 + h1 * h1;
            }
            atomicAdd(&aux[o], s);
            atomicAdd(&aux[64 + o], q);
        }

        // blocked store: ull idx in tile = v*512 + og*128 + th*64 + tp*16 + o4
        ull* dst = (ull*)g_hid + ((size_t)n * 16 + tc) * 12800 + v * 512 + th * 64 + o4;
#pragma unroll
        for (int og = 0; og < 4; og++)
#pragma unroll
            for (int tp = 0; tp < 4; tp++)
                dst[og * 128 + tp * 16] = acc[og][tp];
    }
    __syncthreads();

    if (tid < 64) atomicAdd(&g_sum[tid], aux[tid]);
    else if (tid < 128) atomicAdd(&g_sumsq[tid - 64], aux[tid]);
}

// ---------------------------------------------------------------------------
// kbn: training-mode biased-var BN folded to per-channel scale/shift.
// ---------------------------------------------------------------------------
__global__ void kbn(const float* __restrict__ gamma, const float* __restrict__ beta) {
    int o = threadIdx.x;
    if (o < CC) {
        float m = g_sum[o] * (1.0f / NPOS);
        float var = g_sumsq[o] * (1.0f / NPOS) - m * m;
        float r = rsqrtf(var + 1e-5f);
        float sc = gamma[o] * r;
        g_scale[o] = sc;
        g_shift[o] = beta[o] - m * sc;
    }
}

// ---------------------------------------------------------------------------
// epi: HALF-tile (32 channels) per block -> smem 52.8KB -> 4 blocks/SM,
// occ 100%, grid 4096. Phase 1: read the half's blocked floats (per v one
// contiguous 2KB run), decode into hsm[pos][33] (odd stride: phase-2
// conflict-free). Phase 2: out = relu(hid*scale+shift + x), coalesced.
// ---------------------------------------------------------------------------
__global__ void __launch_bounds__(512, 4) epi(const float* __restrict__ x,
                                              float* __restrict__ out) {
    extern __shared__ float hsm[];            // [400][33]
    float* sc_sh = hsm + POS * HSTR2;
    float* sf_sh = sc_sh + 64;
    int tid = threadIdx.x;
    int bx = blockIdx.x;
    int tc = bx >> 1, h = bx & 1;
    int n = blockIdx.y;

    if (tid < 64) { sc_sh[tid] = g_scale[tid]; sf_sh[tid] = g_shift[tid]; }

    const float4* hb = (const float4*)(g_hid + ((size_t)n * 16 + tc) * TILE);
#pragma unroll 2
    for (int i4 = tid; i4 < 3200; i4 += 512) {
        int v = i4 >> 7, r4 = i4 & 127;
        float4 hv = hb[v * 256 + h * 128 + r4];
        int bf = r4 * 4;
        int og_l = bf >> 8;                   // 0..1
        int th = (bf >> 7) & 1;
        int tp = (bf >> 5) & 3;
        int o4 = (bf >> 1) & 15;              // even
        int ol = og_l * 16 + o4;
        int t = th * 8 + tp * 2;
        float* p = hsm + (t * 25 + v) * HSTR2 + ol;
        p[0] = hv.x;                          // (ol,   t)
        p[25 * HSTR2] = hv.y;                 // (ol,   t+1)
        p[1] = hv.z;                          // (ol+1, t)
        p[25 * HSTR2 + 1] = hv.w;             // (ol+1, t+1)
    }
    __syncthreads();

    if (tid < POS) {
        size_t base = (size_t)n * 409600 + (size_t)h * 32 * 6400 + tc * POS + tid;
        const float* xp = x + base;
        float* op = out + base;
        const float* hrow = hsm + tid * HSTR2;
#pragma unroll 8
        for (int cl = 0; cl < 32; cl++) {
            int c = h * 32 + cl;
            float val = fmaf(hrow[cl], sc_sh[c], sf_sh[c]) + xp[cl * 6400];
            op[cl * 6400] = fmaxf(val, 0.f);
        }
    }
}

extern "C" void kernel_launch(void* const* d_in, const int* in_sizes, int n_in,
                              void* d_out, int out_size) {
    const float* x     = (const float*)d_in[0];
    const float* A     = (const float*)d_in[1];
    const float* GA    = (const float*)d_in[2];
    const float* gw    = (const float*)d_in[7];
    const float* gb    = (const float*)d_in[8];
    const float* gamma = (const float*)d_in[9];
    const float* beta  = (const float*)d_in[10];
    float* out = (float*)d_out;
    (void)in_sizes; (void)n_in; (void)out_size;

    cudaFuncSetAttribute(gemmst, cudaFuncAttributeMaxDynamicSharedMemorySize, GSMEM);
    cudaFuncSetAttribute(epi, cudaFuncAttributeMaxDynamicSharedMemorySize, ESMEM);

    k0a<<<1, 128>>>(A, GA, gb);               // idx 0
    k0b<<<52, 256>>>(gw, 0);                  // idx 1
    k0b<<<52, 256>>>(gw, 13);                 // idx 2
    gemmst<<<dim3(TT / TC, NN), NTHR, GSMEM>>>(x);   // idx 3 -> ncu capture
    kbn<<<1, 64>>>(gamma, beta);
    epi<<<dim3(32, NN), 512, ESMEM>>>(x, out);
}

// round 11
// speedup vs baseline: 1.4849x; 1.0244x over previous
#include <cuda_runtime.h>

#define CC 64
#define TT 256
#define VV 25
#define NN 128
#define TC 16              /* t per block */
#define POS 400            /* TC*VV */
#define NPOS 819200.0f
#define NTHR 416           /* 13 warps */
#define TILE 25600         /* CC*TC*VV floats per (n,tc) tile */
#define XS_FLOATS (CC * POS)           /* 25600 */
#define GSMEM ((XS_FLOATS + 128) * 4)  /* 102912 B */
#define HSTR2 33
#define ESMEM ((POS * HSTR2 + 128) * 4)  /* 53312 B -> 4 blocks/SM */
#define TOTEL 52428800

typedef unsigned long long ull;

// Device globals (no runtime allocation). g_Wf padded +256 so the ping-pong
// prefetch (reads up to c=65) never faults.
__device__ __align__(16) float g_Wf[VV * CC * CC + 256];  // [v][c][o4][og], o=og*16+o4
__device__ __align__(16) float g_B[CC];
__device__ float g_s[75];
__device__ float g_sum[CC];
__device__ float g_sumsq[CC];
__device__ float g_scale[CC];
__device__ float g_shift[CC];
// hidden in BLOCKED layout: [n][tc][v][og][th][tp][o4][j]  (t = th*8+tp*2+j)
__device__ float g_hid[TOTEL];

__device__ __forceinline__ void ffma2(ull& d, ull a, ull b) {
    asm("fma.rn.f32x2 %0, %1, %2, %0;" : "+l"(d) : "l"(a), "l"(b));
}
__device__ __forceinline__ ull packrep(float v) {
    ull r; asm("mov.b64 %0, {%1,%1};" : "=l"(r) : "f"(v)); return r;
}
__device__ __forceinline__ void unpack2(ull p, float& a, float& b) {
    asm("mov.b64 {%0,%1}, %2;" : "=f"(a), "=f"(b) : "l"(p));
}

// ---------------------------------------------------------------------------
// k0a: softmax rows sum to 1 -> attention collapses to s_i[v] = 1+sum_w(A+GA).
// Compute g_s, B = sum_i gb[i], zero stat accumulators. One tiny block.
// ---------------------------------------------------------------------------
__global__ void k0a(const float* __restrict__ A, const float* __restrict__ GA,
                    const float* __restrict__ gb) {
    int tid = threadIdx.x;
    if (tid < 75) {
        const float* a = A + tid * 25;
        const float* g = GA + tid * 25;
        float s = 1.f;
        for (int w = 0; w < 25; w++) s += a[w] + g[w];
        g_s[tid] = s;
    }
    if (tid < CC) {
        g_sum[tid] = 0.f;
        g_sumsq[tid] = 0.f;
        float b = 0.f;
        for (int i = 0; i < 3; i++) b += gb[i * CC + tid];
        g_B[tid] = b;
    }
}

// ---------------------------------------------------------------------------
// k0b: build folded weights for v in [vbase, vbase+13):
//   g_Wf[((v*64+c)*16+o4)*4+og] = sum_i s_i[v]*gw[i][o][c], o = og*16+o4.
// Two instances (vbase 0, 13) so gemmst sits at captured launch index 3.
// ---------------------------------------------------------------------------
__global__ void k0b(const float* __restrict__ gw, int vbase) {
    __shared__ float s_sh[75];
    int tid = threadIdx.x;
    if (tid < 75) s_sh[tid] = g_s[tid];
    __syncthreads();
    int nv = (vbase + 13 <= VV) ? 13 : (VV - vbase);
    for (int li = blockIdx.x * blockDim.x + tid; li < nv * CC * CC;
         li += gridDim.x * blockDim.x) {
        int og = li & 3;
        int o4 = (li >> 2) & 15;
        int c = (li >> 6) & 63;
        int v = vbase + (li >> 12);
        int o = og * 16 + o4;
        float w = 0.f;
        for (int i = 0; i < 3; i++)
            w += s_sh[i * 25 + v] * gw[(i * CC + o) * CC + c];
        g_Wf[(size_t)v * 4096 + (li & 4095)] = w;
    }
}

// ---------------------------------------------------------------------------
// gemmst: block=(tc of 16 t, n), 13 warps, occupancy 2. Warp = vertex v
// (rounds v, v+13). lane = (o4, th). f32x2 packs T-PAIRS j=t&1:
// acc[og][tp] covers o=og*16+o4, t=th*8+tp*2+{0,1}.
// xs laid [c][tp][v][4] (th,j adjacent) -> every mainloop LDS.64 is ONE
// wavefront. STAGING is conflict-free: each thread owns one (tp,v) float4
// slot, gathers its 4 t-values with coalesced LDG.32s, writes ONE contiguous
// STS.128 (wavefront floor) -- replaces the 16-way-conflicted scatter.
// Weights: one LDG.128/thread-channel in a copy-free ping-pong (distance
// 2 channels > L2 hit latency). Hidden leaves in registers as blocked
// STG.64. Stats via smem atomics -> global atomics.
// ---------------------------------------------------------------------------
__global__ void __launch_bounds__(NTHR, 2)
gemmst(const float* __restrict__ x) {
    extern __shared__ float smem[];
    float* xs = smem;                 // [c][tp][v][4]
    float* aux = smem + XS_FLOATS;    // stats[128]
    int tid = threadIdx.x;
    int tc = blockIdx.x, n = blockIdx.y;

    if (tid < 128) aux[tid] = 0.f;

    // conflict-free staging: thread -> (cq, tp, v); 16 channels each.
    // float4 slot {t0, t0+1, t0+8, t0+9}, t0 = tp*2.
    if (tid < 400) {
        int cq = tid / 100;                    // 0..3
        int pos = tid - cq * 100;              // 0..99
        int tp = pos / 25, v = pos - tp * 25;
        const float* sc = x + (size_t)n * 409600 + tc * POS
                          + (size_t)(cq * 16) * 6400 + tp * 50 + v;
        float4* dst4 = (float4*)xs + cq * 1600 + tp * 25 + v;
#pragma unroll 4
        for (int cc = 0; cc < 16; cc++) {
            float4 f;
            f.x = sc[0];                       // t0   (th0,j0)
            f.y = sc[25];                      // t0+1 (th0,j1)
            f.z = sc[200];                     // t0+8 (th1,j0)
            f.w = sc[225];                     // t0+9 (th1,j1)
            dst4[cc * 100] = f;
            sc += 6400;
        }
    }
    __syncthreads();

    int warp = tid >> 5, lane = tid & 31;
    int o4 = lane & 15, th = lane >> 4;

    for (int v = warp; v < VV; v += 13) {
        ull acc[4][4];                 // [og][tp]
#pragma unroll
        for (int og = 0; og < 4; og++) {
            ull b = packrep(g_B[og * 16 + o4]);
#pragma unroll
            for (int tp = 0; tp < 4; tp++) acc[og][tp] = b;
        }

        const float4* wp = (const float4*)(g_Wf + (size_t)v * 4096) + o4;  // + c*16
        const ull* xb = (const ull*)xs + v * 2 + th;                       // + c*200 + tp*50

        auto dochan = [&](int c, float4 w) {
            ull w0 = packrep(w.x), w1 = packrep(w.y);
            ull w2 = packrep(w.z), w3 = packrep(w.w);
#pragma unroll
            for (int tp = 0; tp < 4; tp++) {
                ull xv = xb[c * 200 + tp * 50];
                ffma2(acc[0][tp], w0, xv);
                ffma2(acc[1][tp], w1, xv);
                ffma2(acc[2][tp], w2, xv);
                ffma2(acc[3][tp], w3, xv);
            }
        };

        float4 wA = wp[0];
        float4 wB = wp[16];
#pragma unroll 2
        for (int cc = 0; cc < 32; cc++) {
            int c0 = 2 * cc;
            dochan(c0, wA);
            wA = wp[(c0 + 2) * 16];        // reload in place: no copy movs
            dochan(c0 + 1, wB);
            wB = wp[(c0 + 3) * 16];        // (padded: c<=65 never faults)
        }

        // stats (every (o,t,v) counted exactly once grid-wide)
#pragma unroll
        for (int og = 0; og < 4; og++) {
            int o = og * 16 + o4;
            float s = 0.f, q = 0.f;
#pragma unroll
            for (int tp = 0; tp < 4; tp++) {
                float h0, h1;
                unpack2(acc[og][tp], h0, h1);
                s += h0 + h1;
                q += h0 * h0 + h1 * h1;
            }
            atomicAdd(&aux[o], s);
            atomicAdd(&aux[64 + o], q);
        }

        // blocked store: ull idx in tile = v*512 + og*128 + th*64 + tp*16 + o4
        ull* dst = (ull*)g_hid + ((size_t)n * 16 + tc) * 12800 + v * 512 + th * 64 + o4;
#pragma unroll
        for (int og = 0; og < 4; og++)
#pragma unroll
            for (int tp = 0; tp < 4; tp++)
                dst[og * 128 + tp * 16] = acc[og][tp];
    }
    __syncthreads();

    if (tid < 64) atomicAdd(&g_sum[tid], aux[tid]);
    else if (tid < 128) atomicAdd(&g_sumsq[tid - 64], aux[tid]);
}

// ---------------------------------------------------------------------------
// kbn: training-mode biased-var BN folded to per-channel scale/shift.
// ---------------------------------------------------------------------------
__global__ void kbn(const float* __restrict__ gamma, const float* __restrict__ beta) {
    int o = threadIdx.x;
    if (o < CC) {
        float m = g_sum[o] * (1.0f / NPOS);
        float var = g_sumsq[o] * (1.0f / NPOS) - m * m;
        float r = rsqrtf(var + 1e-5f);
        float sc = gamma[o] * r;
        g_scale[o] = sc;
        g_shift[o] = beta[o] - m * sc;
    }
}

// ---------------------------------------------------------------------------
// epi: HALF-tile (32 channels) per block -> smem 52.8KB -> 4 blocks/SM,
// occ 100%, grid 4096. Phase 1: read the half's blocked floats (per v one
// contiguous 2KB run), decode into hsm[pos][33] (odd stride: phase-2
// conflict-free). Phase 2: out = relu(hid*scale+shift + x), coalesced.
// ---------------------------------------------------------------------------
__global__ void __launch_bounds__(512, 4) epi(const float* __restrict__ x,
                                              float* __restrict__ out) {
    extern __shared__ float hsm[];            // [400][33]
    float* sc_sh = hsm + POS * HSTR2;
    float* sf_sh = sc_sh + 64;
    int tid = threadIdx.x;
    int bx = blockIdx.x;
    int tc = bx >> 1, h = bx & 1;
    int n = blockIdx.y;

    if (tid < 64) { sc_sh[tid] = g_scale[tid]; sf_sh[tid] = g_shift[tid]; }

    const float4* hb = (const float4*)(g_hid + ((size_t)n * 16 + tc) * TILE);
#pragma unroll 2
    for (int i4 = tid; i4 < 3200; i4 += 512) {
        int v = i4 >> 7, r4 = i4 & 127;
        float4 hv = hb[v * 256 + h * 128 + r4];
        int bf = r4 * 4;
        int og_l = bf >> 8;                   // 0..1
        int th = (bf >> 7) & 1;
        int tp = (bf >> 5) & 3;
        int o4 = (bf >> 1) & 15;              // even
        int ol = og_l * 16 + o4;
        int t = th * 8 + tp * 2;
        float* p = hsm + (t * 25 + v) * HSTR2 + ol;
        p[0] = hv.x;                          // (ol,   t)
        p[25 * HSTR2] = hv.y;                 // (ol,   t+1)
        p[1] = hv.z;                          // (ol+1, t)
        p[25 * HSTR2 + 1] = hv.w;             // (ol+1, t+1)
    }
    __syncthreads();

    if (tid < POS) {
        size_t base = (size_t)n * 409600 + (size_t)h * 32 * 6400 + tc * POS + tid;
        const float* xp = x + base;
        float* op = out + base;
        const float* hrow = hsm + tid * HSTR2;
#pragma unroll 8
        for (int cl = 0; cl < 32; cl++) {
            int c = h * 32 + cl;
            float val = fmaf(hrow[cl], sc_sh[c], sf_sh[c]) + xp[cl * 6400];
            op[cl * 6400] = fmaxf(val, 0.f);
        }
    }
}

extern "C" void kernel_launch(void* const* d_in, const int* in_sizes, int n_in,
                              void* d_out, int out_size) {
    const float* x     = (const float*)d_in[0];
    const float* A     = (const float*)d_in[1];
    const float* GA    = (const float*)d_in[2];
    const float* gw    = (const float*)d_in[7];
    const float* gb    = (const float*)d_in[8];
    const float* gamma = (const float*)d_in[9];
    const float* beta  = (const float*)d_in[10];
    float* out = (float*)d_out;
    (void)in_sizes; (void)n_in; (void)out_size;

    cudaFuncSetAttribute(gemmst, cudaFuncAttributeMaxDynamicSharedMemorySize, GSMEM);
    cudaFuncSetAttribute(epi, cudaFuncAttributeMaxDynamicSharedMemorySize, ESMEM);

    k0a<<<1, 128>>>(A, GA, gb);               // idx 0
    k0b<<<52, 256>>>(gw, 0);                  // idx 1
    k0b<<<52, 256>>>(gw, 13);                 // idx 2
    gemmst<<<dim3(TT / TC, NN), NTHR, GSMEM>>>(x);   // idx 3 -> ncu capture
    kbn<<<1, 64>>>(gamma, beta);
    epi<<<dim3(32, NN), 512, ESMEM>>>(x, out);
}